// round 11
// baseline (speedup 1.0000x reference)
#include <cuda_runtime.h>
#include <cuda_fp16.h>
#include <math.h>
#include <stdint.h>

#define H 128
#define NGR 256
#define NCLS 10
#define NMAX 50048
#define EMAX 600064
#define NB_STATS 256
#define SCAN_BLK 512
#define MAX_SB ((NMAX + SCAN_BLK - 1) / SCAN_BLK)

#define ST32 68                         // uint32 stride of fp16 smem rows (136 halves)
#define SMEM_MM (4 * 128 * ST32 * 4)    // AsH, AsL, BsH, BsL = 139264 B
#define PGRID 148                       // persistent GEMM grid (1 CTA/SM)

// ---------------- device scratch (static; no allocation allowed) ----------------
__device__ float g_bufA[(size_t)NMAX * H];               // GEMM output p (fp32)
__device__ __align__(16) __half g_XH[(size_t)NMAX * H];  // activations hi
__device__ __align__(16) __half g_XL[(size_t)NMAX * H];  // activations lo
__device__ float g_dinv[NMAX];
__device__ int   g_deg[NMAX];
__device__ int   g_rowptr[NMAX + 1];
__device__ int   g_cursor[NMAX];
__device__ int   g_srcs[EMAX];
__device__ int   g_bsum[MAX_SB + 1];
__device__ float g_psum[NB_STATS * H];
__device__ float g_psq[NB_STATS * H];
__device__ float g_colsum[H];
__device__ float g_colsq[H];
__device__ float g_svec[H];
__device__ float g_tvec[H];
__device__ float g_Wf[H * H];                // folded fc weight
__device__ __align__(16) __half g_Bh[H * H]; // conv weight fp16 hi, [n][k]
__device__ __align__(16) __half g_Bl[H * H]; // fp16 lo, [n][k]
__device__ float g_cvec[H];
__device__ float g_bf[H];
__device__ float g_pool[NGR * H];
__device__ int   g_flags[2];

// ---------------- helpers ----------------
__device__ __forceinline__ uint32_t pack2(__half a, __half b) {
    return (uint32_t)__half_as_ushort(a) | ((uint32_t)__half_as_ushort(b) << 16);
}
__device__ __forceinline__ void split16(float x, __half& hi, __half& lo) {
    hi = __float2half_rn(x);
    lo = __float2half_rn(x - __half2float(hi));
}
__device__ __forceinline__ void mma16(float* acc, uint32_t a0, uint32_t a1, uint32_t a2,
                                      uint32_t a3, uint32_t b0, uint32_t b1) {
    asm volatile(
        "mma.sync.aligned.m16n8k16.row.col.f32.f16.f16.f32 "
        "{%0,%1,%2,%3},{%4,%5,%6,%7},{%8,%9},{%0,%1,%2,%3};"
        : "+f"(acc[0]), "+f"(acc[1]), "+f"(acc[2]), "+f"(acc[3])
        : "r"(a0), "r"(a1), "r"(a2), "r"(a3), "r"(b0), "r"(b1));
}

// ---------------- dtype-flexible index load ----------------
__device__ __forceinline__ int edge_idx(const void* p, long long i) {
    return g_flags[0] ? (int)((const long long*)p)[i] : ((const int*)p)[i];
}

__global__ void k_detect(const void* ei, const void* bt, int E, int N) {
    if (threadIdx.x == 0 && blockIdx.x == 0) {
        const unsigned long long* e64 = (const unsigned long long*)ei;
        int f = 1;
        for (int j = 0; j < 32; j++)
            if (e64[j] >= (1ULL << 31)) { f = 0; break; }
        g_flags[0] = f;
        const unsigned long long* b64 = (const unsigned long long*)bt;
        int f2 = 1;
        int half = N / 2;
        for (int j = half - 32; j < half; j++)
            if (b64[j] >= (1ULL << 31)) { f2 = 0; break; }
        g_flags[1] = f2;
    }
}

__global__ void k_zero(int N) {
    int tot = (N > NGR * H) ? N : (NGR * H);
    for (int i = blockIdx.x * blockDim.x + threadIdx.x; i < tot; i += gridDim.x * blockDim.x) {
        if (i < N) g_deg[i] = 0;
        if (i < NGR * H) g_pool[i] = 0.f;
        if (i < H) { g_colsum[i] = 0.f; g_colsq[i] = 0.f; }
    }
}

__global__ void k_hist(const void* ei, int E) {
    int e = blockIdx.x * blockDim.x + threadIdx.x;
    if (e < E) atomicAdd(&g_deg[edge_idx(ei, (long long)E + e)], 1);
}

// ---------------- CSR build (scan1 also emits dinv) ----------------
__global__ void k_scan1(int N) {
    __shared__ int sh[SCAN_BLK];
    int t = threadIdx.x;
    int i = blockIdx.x * SCAN_BLK + t;
    int v = (i < N) ? g_deg[i] : 0;
    if (i < N) g_dinv[i] = rsqrtf((float)v + 1.0f);
    sh[t] = v;
    __syncthreads();
    for (int off = 1; off < SCAN_BLK; off <<= 1) {
        int add = (t >= off) ? sh[t - off] : 0;
        __syncthreads();
        sh[t] += add;
        __syncthreads();
    }
    if (i < N) g_rowptr[i] = sh[t] - v;
    if (t == SCAN_BLK - 1) g_bsum[blockIdx.x] = sh[t];
}

__global__ void k_scan2(int nb) {
    if (threadIdx.x == 0 && blockIdx.x == 0) {
        int acc = 0;
        for (int b = 0; b < nb; b++) { int v = g_bsum[b]; g_bsum[b] = acc; acc += v; }
    }
}

__global__ void k_scan3(int N, int E) {
    int i = blockIdx.x * blockDim.x + threadIdx.x;
    if (i < N) {
        int r = g_rowptr[i] + g_bsum[i / SCAN_BLK];
        g_rowptr[i] = r;
        g_cursor[i] = r;
    }
    if (i == 0) g_rowptr[N] = E;
}

__global__ void k_fill(const void* ei, int E) {
    int e = blockIdx.x * blockDim.x + threadIdx.x;
    if (e < E) {
        int s = edge_idx(ei, e);
        int d = edge_idx(ei, (long long)E + e);
        g_srcs[atomicAdd(&g_cursor[d], 1)] = s;
    }
}

// ---------------- BN statistics over x (layer 0 only) ----------------
__global__ void k_stats(const float* __restrict__ h, int N) {
    int j = threadIdx.x;
    int b = blockIdx.x;
    float s = 0.f, q = 0.f;
    for (int r = b; r < N; r += NB_STATS) {
        float v = h[(size_t)r * H + j];
        s += v; q += v * v;
    }
    g_psum[b * H + j] = s;
    g_psq[b * H + j]  = q;
}

// fold stage 1: finalize BN stats -> s,t vectors; self-zero fused stat accumulators
__global__ void k_fold1(const float* __restrict__ bias_in, const float* __restrict__ gamma,
                        const float* __restrict__ beta, int Nrows, int frombuckets) {
    int j = threadIdx.x;
    float s = 0.f, q = 0.f;
    if (frombuckets) {
        for (int b = 0; b < NB_STATS; b++) { s += g_psum[b * H + j]; q += g_psq[b * H + j]; }
    } else {
        s = g_colsum[j]; q = g_colsq[j];
        g_colsum[j] = 0.f; g_colsq[j] = 0.f;
    }
    float mean = s / (float)Nrows;
    float var  = q / (float)Nrows - mean * mean;
    float sj = rsqrtf(var + 1e-5f) * gamma[j];
    g_svec[j] = sj;
    g_tvec[j] = beta[j] - mean * sj;
    g_bf[j] = bias_in[j];
}

// fold stage 2 (parallel, 128 blocks): weight split image [n][k] + cvec
__global__ void k_fold2(const float* __restrict__ W) {
    __shared__ float red[4];
    int n = blockIdx.x, k = threadIdx.x;
    float wkn = W[k * H + n];
    float w = g_svec[k] * wkn;
    __half hh, hl;
    split16(w, hh, hl);
    g_Bh[n * H + k] = hh;
    g_Bl[n * H + k] = hl;
    float c = g_tvec[k] * wkn;
#pragma unroll
    for (int o = 16; o; o >>= 1) c += __shfl_xor_sync(0xffffffffu, c, o);
    if ((k & 31) == 0) red[k >> 5] = c;
    __syncthreads();
    if (k == 0) g_cvec[n] = red[0] + red[1] + red[2] + red[3];
}

// gate_W1 -> transposed split image (no BN scale, no cvec)
__global__ void k_prepgate(const float* __restrict__ W) {
    int n = blockIdx.x, k = threadIdx.x;
    float w = W[k * H + n];
    __half hh, hl;
    split16(w, hh, hl);
    g_Bh[n * H + k] = hh;
    g_Bl[n * H + k] = hl;
}

// ---------------- persistent tensor-core GEMM, fp16 3-term split ----------------
// grid=PGRID, 512 threads; B staged once; tiles strided.
// mode 0: A = fp32 (x), epilogue acc+cvec
// mode 1: A = fp16 hi/lo images, epilogue acc+cvec
// mode 2: A = fp16 hi/lo images, epilogue relu(acc+bias)
__global__ void __launch_bounds__(512, 1)
k_mm_mma(const float* __restrict__ A32, const __half* __restrict__ AH,
         const __half* __restrict__ AL, const float* __restrict__ bias,
         float* __restrict__ out, int nrows, int ntiles, int mode) {
    extern __shared__ uint32_t smu[];
    uint32_t* AsH = smu;
    uint32_t* AsL = smu + 128 * ST32;
    uint32_t* BsH = smu + 2 * 128 * ST32;
    uint32_t* BsL = smu + 3 * 128 * ST32;
    int tid = threadIdx.x;
    int wid = tid >> 5, lane = tid & 31;
    int wm = wid & 3, wn = wid >> 2;
    int g = lane >> 2, t = lane & 3;

    // ---- stage B once ----
    {
        const uint4* bh4 = (const uint4*)g_Bh;
        const uint4* bl4 = (const uint4*)g_Bl;
#pragma unroll
        for (int i = 0; i < 4; i++) {
            int f = i * 512 + tid;
            int n = f >> 4;
            int c = (f & 15) << 2;
            uint4 vh = bh4[f];
            uint4 vl = bl4[f];
            *(uint4*)&BsH[n * ST32 + c] = vh;
            *(uint4*)&BsL[n * ST32 + c] = vl;
        }
    }

    for (int tile = blockIdx.x; tile < ntiles; tile += gridDim.x) {
        int row0 = tile * 128;
        uint4 hv[4], lv[4];
        if (mode == 0) {
#pragma unroll
            for (int i = 0; i < 4; i++) {
                int f = i * 512 + tid;
                int r = f >> 4;
                int c8 = (f & 15) << 3;
                int gr = row0 + r;
                float4 va = make_float4(0.f, 0.f, 0.f, 0.f);
                float4 vb = make_float4(0.f, 0.f, 0.f, 0.f);
                if (gr < nrows) {
                    va = *(const float4*)&A32[(size_t)gr * H + c8];
                    vb = *(const float4*)&A32[(size_t)gr * H + c8 + 4];
                }
                __half h0, l0, h1, l1, h2, l2, h3, l3, h4, l4, h5, l5, h6, l6, h7, l7;
                split16(va.x, h0, l0); split16(va.y, h1, l1);
                split16(va.z, h2, l2); split16(va.w, h3, l3);
                split16(vb.x, h4, l4); split16(vb.y, h5, l5);
                split16(vb.z, h6, l6); split16(vb.w, h7, l7);
                hv[i] = make_uint4(pack2(h0, h1), pack2(h2, h3), pack2(h4, h5), pack2(h6, h7));
                lv[i] = make_uint4(pack2(l0, l1), pack2(l2, l3), pack2(l4, l5), pack2(l6, l7));
            }
        } else {
            const uint4* ah4 = (const uint4*)AH;
            const uint4* al4 = (const uint4*)AL;
#pragma unroll
            for (int i = 0; i < 4; i++) {
                int f = i * 512 + tid;
                int r = f >> 4;
                int cu = f & 15;
                int gr = row0 + r;
                if (gr < nrows) {
                    hv[i] = ah4[(size_t)gr * 16 + cu];
                    lv[i] = al4[(size_t)gr * 16 + cu];
                } else {
                    hv[i] = make_uint4(0, 0, 0, 0);
                    lv[i] = make_uint4(0, 0, 0, 0);
                }
            }
        }
        __syncthreads();     // prior tile's LDS reads complete (covers B STS on iter 0)
#pragma unroll
        for (int i = 0; i < 4; i++) {
            int f = i * 512 + tid;
            int r = f >> 4;
            int c = (f & 15) << 2;
            *(uint4*)&AsH[r * ST32 + c] = hv[i];
            *(uint4*)&AsL[r * ST32 + c] = lv[i];
        }
        __syncthreads();

        float acc[2][4][4];
#pragma unroll
        for (int mf = 0; mf < 2; mf++)
#pragma unroll
            for (int nf = 0; nf < 4; nf++)
#pragma unroll
                for (int k = 0; k < 4; k++) acc[mf][nf][k] = 0.f;

#pragma unroll
        for (int ki = 0; ki < 8; ki++) {
            int k0 = ki * 8;
            uint32_t ah[2][4], al[2][4];
#pragma unroll
            for (int mf = 0; mf < 2; mf++) {
                int rA = (wm * 32 + mf * 16 + g) * ST32 + k0 + t;
                ah[mf][0] = AsH[rA];             ah[mf][1] = AsH[rA + 8 * ST32];
                ah[mf][2] = AsH[rA + 4];         ah[mf][3] = AsH[rA + 8 * ST32 + 4];
                al[mf][0] = AsL[rA];             al[mf][1] = AsL[rA + 8 * ST32];
                al[mf][2] = AsL[rA + 4];         al[mf][3] = AsL[rA + 8 * ST32 + 4];
            }
            uint32_t bh[4][2], bl[4][2];
#pragma unroll
            for (int nf = 0; nf < 4; nf++) {
                int rB = (wn * 32 + nf * 8 + g) * ST32 + k0 + t;
                bh[nf][0] = BsH[rB];             bh[nf][1] = BsH[rB + 4];
                bl[nf][0] = BsL[rB];             bl[nf][1] = BsL[rB + 4];
            }
#pragma unroll
            for (int mf = 0; mf < 2; mf++)
#pragma unroll
                for (int nf = 0; nf < 4; nf++) {
                    mma16(acc[mf][nf], ah[mf][0], ah[mf][1], ah[mf][2], ah[mf][3],
                          bh[nf][0], bh[nf][1]);
                    mma16(acc[mf][nf], al[mf][0], al[mf][1], al[mf][2], al[mf][3],
                          bh[nf][0], bh[nf][1]);
                    mma16(acc[mf][nf], ah[mf][0], ah[mf][1], ah[mf][2], ah[mf][3],
                          bl[nf][0], bl[nf][1]);
                }
        }

        // ---- epilogue ----
#pragma unroll
        for (int mf = 0; mf < 2; mf++) {
            int r0 = row0 + wm * 32 + mf * 16 + g;
            int r1 = r0 + 8;
#pragma unroll
            for (int nf = 0; nf < 4; nf++) {
                int col = wn * 32 + nf * 8 + t * 2;
                float* a = acc[mf][nf];
                if (mode != 2) {
                    float c0 = g_cvec[col], c1 = g_cvec[col + 1];
                    if (r0 < nrows)
                        *(float2*)&out[(size_t)r0 * H + col] = make_float2(a[0] + c0, a[1] + c1);
                    if (r1 < nrows)
                        *(float2*)&out[(size_t)r1 * H + col] = make_float2(a[2] + c0, a[3] + c1);
                } else {
                    float b0 = bias[col], b1 = bias[col + 1];
                    if (r0 < nrows)
                        *(float2*)&out[(size_t)r0 * H + col] =
                            make_float2(fmaxf(a[0] + b0, 0.f), fmaxf(a[1] + b1, 0.f));
                    if (r1 < nrows)
                        *(float2*)&out[(size_t)r1 * H + col] =
                            make_float2(fmaxf(a[2] + b0, 0.f), fmaxf(a[3] + b1, 0.f));
                }
            }
        }
    }
}

// ---------------- CSR gather + relu + fp16 hi/lo output + fused BN stats ----------------
// h[i] = relu( dinv_i * (dinv_i*p_i + sum_e dinv_s*p_s) + conv_bias )
#define GW 8
__global__ void k_gather(const float* __restrict__ p, __half* __restrict__ oh,
                         __half* __restrict__ ol, int N) {
    __shared__ float sv[GW][H], sq2[GW][H];
    int warp = threadIdx.x >> 5, lane = threadIdx.x & 31;
    int w = blockIdx.x * GW + warp;
    float4 o = make_float4(0.f, 0.f, 0.f, 0.f);
    if (w < N) {
        float dw = g_dinv[w];
        float4 self = *(const float4*)&p[(size_t)w * H + lane * 4];
        float4 acc = make_float4(self.x * dw, self.y * dw, self.z * dw, self.w * dw);
        int beg = g_rowptr[w], end = g_rowptr[w + 1];
        int e = beg;
        for (; e + 3 < end; e += 4) {
            int s0 = g_srcs[e], s1 = g_srcs[e + 1], s2 = g_srcs[e + 2], s3 = g_srcs[e + 3];
            float d0 = g_dinv[s0], d1 = g_dinv[s1], d2 = g_dinv[s2], d3 = g_dinv[s3];
            float4 v0 = *(const float4*)&p[(size_t)s0 * H + lane * 4];
            float4 v1 = *(const float4*)&p[(size_t)s1 * H + lane * 4];
            float4 v2 = *(const float4*)&p[(size_t)s2 * H + lane * 4];
            float4 v3 = *(const float4*)&p[(size_t)s3 * H + lane * 4];
            acc.x = fmaf(v0.x, d0, acc.x); acc.y = fmaf(v0.y, d0, acc.y);
            acc.z = fmaf(v0.z, d0, acc.z); acc.w = fmaf(v0.w, d0, acc.w);
            acc.x = fmaf(v1.x, d1, acc.x); acc.y = fmaf(v1.y, d1, acc.y);
            acc.z = fmaf(v1.z, d1, acc.z); acc.w = fmaf(v1.w, d1, acc.w);
            acc.x = fmaf(v2.x, d2, acc.x); acc.y = fmaf(v2.y, d2, acc.y);
            acc.z = fmaf(v2.z, d2, acc.z); acc.w = fmaf(v2.w, d2, acc.w);
            acc.x = fmaf(v3.x, d3, acc.x); acc.y = fmaf(v3.y, d3, acc.y);
            acc.z = fmaf(v3.z, d3, acc.z); acc.w = fmaf(v3.w, d3, acc.w);
        }
        for (; e < end; e++) {
            int s = g_srcs[e];
            float ds = g_dinv[s];
            float4 v = *(const float4*)&p[(size_t)s * H + lane * 4];
            acc.x = fmaf(v.x, ds, acc.x); acc.y = fmaf(v.y, ds, acc.y);
            acc.z = fmaf(v.z, ds, acc.z); acc.w = fmaf(v.w, ds, acc.w);
        }
        float4 bb = *(const float4*)&g_bf[lane * 4];
        o.x = fmaxf(fmaf(acc.x, dw, bb.x), 0.f);
        o.y = fmaxf(fmaf(acc.y, dw, bb.y), 0.f);
        o.z = fmaxf(fmaf(acc.z, dw, bb.z), 0.f);
        o.w = fmaxf(fmaf(acc.w, dw, bb.w), 0.f);
        __half h0, l0, h1, l1, h2, l2, h3, l3;
        split16(o.x, h0, l0); split16(o.y, h1, l1);
        split16(o.z, h2, l2); split16(o.w, h3, l3);
        *(uint2*)&oh[(size_t)w * H + lane * 4] = make_uint2(pack2(h0, h1), pack2(h2, h3));
        *(uint2*)&ol[(size_t)w * H + lane * 4] = make_uint2(pack2(l0, l1), pack2(l2, l3));
    }
    // fused column stats (sum / sumsq) for the next layer's BN
    int c0 = lane * 4;
    sv[warp][c0 + 0] = o.x;  sq2[warp][c0 + 0] = o.x * o.x;
    sv[warp][c0 + 1] = o.y;  sq2[warp][c0 + 1] = o.y * o.y;
    sv[warp][c0 + 2] = o.z;  sq2[warp][c0 + 2] = o.z * o.z;
    sv[warp][c0 + 3] = o.w;  sq2[warp][c0 + 3] = o.w * o.w;
    __syncthreads();
    int tt = threadIdx.x;
    if (tt < H) {
        float s = 0.f;
#pragma unroll
        for (int i = 0; i < GW; i++) s += sv[i][tt];
        atomicAdd(&g_colsum[tt], s);
    } else {
        int c = tt - H;
        float s = 0.f;
#pragma unroll
        for (int i = 0; i < GW; i++) s += sq2[i][c];
        atomicAdd(&g_colsq[c], s);
    }
}

// ---------------- gate scalar + weighted pooling (reads hi/lo activations) ----------------
__global__ void k_gatepool(const float* __restrict__ r, const __half* __restrict__ hh,
                           const __half* __restrict__ hl, const float* __restrict__ w2,
                           const float* __restrict__ b2, const void* batch, int N) {
    int w = (blockIdx.x * blockDim.x + threadIdx.x) >> 5;
    int lane = threadIdx.x & 31;
    if (w >= N) return;
    float4 rv = *(const float4*)&r[(size_t)w * H + lane * 4];
    float4 wv = *(const float4*)&w2[lane * 4];
    float d = rv.x * wv.x + rv.y * wv.y + rv.z * wv.z + rv.w * wv.w;
#pragma unroll
    for (int o = 16; o; o >>= 1) d += __shfl_xor_sync(0xffffffffu, d, o);
    float gate = 1.f / (1.f + expf(-(d + b2[0])));
    int b = g_flags[1] ? (int)((const long long*)batch)[w] : ((const int*)batch)[w];
    const __half2* ph = (const __half2*)(hh + (size_t)w * H) + lane * 2;
    const __half2* pl = (const __half2*)(hl + (size_t)w * H) + lane * 2;
    float2 a0 = __half22float2(ph[0]), a1 = __half22float2(ph[1]);
    float2 c0 = __half22float2(pl[0]), c1 = __half22float2(pl[1]);
    float4 hv = make_float4(a0.x + c0.x, a0.y + c0.y, a1.x + c1.x, a1.y + c1.y);
    float* dst = &g_pool[b * H + lane * 4];
    atomicAdd(dst + 0, hv.x * gate);
    atomicAdd(dst + 1, hv.y * gate);
    atomicAdd(dst + 2, hv.z * gate);
    atomicAdd(dst + 3, hv.w * gate);
}

// ---------------- BN over pooled graphs, folded into fc ----------------
__global__ void k_foldfc(const float* __restrict__ fcW, const float* __restrict__ fcb,
                         const float* __restrict__ gg, const float* __restrict__ gb) {
    int j = threadIdx.x;
    float s = 0.f, q = 0.f;
    for (int r = 0; r < NGR; r++) {
        float v = g_pool[r * H + j];
        s += v; q += v * v;
    }
    float mean = s / (float)NGR;
    float var = q / (float)NGR - mean * mean;
    float sj = rsqrtf(var + 1e-5f) * gg[j];
    float tj = gb[j] - mean * sj;
    __shared__ float ssh[H], tsh[H];
    ssh[j] = sj;
    tsh[j] = tj;
    __syncthreads();
    float bb = fcb[j];
#pragma unroll 4
    for (int r = 0; r < H; r++) {
        float wrj = fcW[r * H + j];
        g_Wf[r * H + j] = ssh[r] * wrj;
        bb += tsh[r] * wrj;
    }
    g_bf[j] = bb;
}

// ---------------- fc + classifier + log_softmax ----------------
__global__ void k_final(const float* __restrict__ clsW, const float* __restrict__ clsb,
                        float* __restrict__ out) {
    __shared__ float gs[H], ys[H], ls[NCLS];
    int g = blockIdx.x, t = threadIdx.x;
    gs[t] = g_pool[g * H + t];
    __syncthreads();
    float a = g_bf[t];
#pragma unroll 8
    for (int j = 0; j < H; j++) a += gs[j] * g_Wf[j * H + t];
    ys[t] = fmaxf(a, 0.f);
    __syncthreads();
    if (t < NCLS) {
        float l = clsb[t];
        for (int k = 0; k < H; k++) l += ys[k] * clsW[k * NCLS + t];
        ls[t] = l;
    }
    __syncthreads();
    if (t == 0) {
        float m = ls[0];
        for (int c = 1; c < NCLS; c++) m = fmaxf(m, ls[c]);
        float se = 0.f;
        for (int c = 0; c < NCLS; c++) se += expf(ls[c] - m);
        float lse = m + logf(se);
        for (int c = 0; c < NCLS; c++) out[g * NCLS + c] = ls[c] - lse;
    }
}

// ---------------- host orchestration ----------------
extern "C" void kernel_launch(void* const* d_in, const int* in_sizes, int n_in,
                              void* d_out, int out_size) {
    const float* x           = (const float*)d_in[0];
    const void*  ei          = d_in[1];
    const void*  batch       = d_in[2];
    const float* bn_feat_g   = (const float*)d_in[3];
    const float* bn_feat_b   = (const float*)d_in[4];
    const float* conv_feat_W = (const float*)d_in[5];
    const float* conv_feat_b = (const float*)d_in[6];
    const float* conv_W      = (const float*)d_in[7];
    const float* conv_b      = (const float*)d_in[8];
    const float* bn_conv_g   = (const float*)d_in[9];
    const float* bn_conv_b   = (const float*)d_in[10];
    const float* gate_W1     = (const float*)d_in[11];
    const float* gate_b1     = (const float*)d_in[12];
    const float* gate_W2     = (const float*)d_in[13];
    const float* gate_b2     = (const float*)d_in[14];
    const float* fc_W        = (const float*)d_in[15];
    const float* fc_b        = (const float*)d_in[16];
    const float* bn_fc_g     = (const float*)d_in[17];
    const float* bn_fc_b     = (const float*)d_in[18];
    const float* cls_W       = (const float*)d_in[19];
    const float* cls_b       = (const float*)d_in[20];

    int N = in_sizes[0] / H;
    int E = in_sizes[1] / 2;

    float* bufA = nullptr;
    __half *xh = nullptr, *xl = nullptr;
    cudaGetSymbolAddress((void**)&bufA, g_bufA);
    cudaGetSymbolAddress((void**)&xh, g_XH);
    cudaGetSymbolAddress((void**)&xl, g_XL);

    cudaFuncSetAttribute(k_mm_mma, cudaFuncAttributeMaxDynamicSharedMemorySize, SMEM_MM);

    int nb = (N + SCAN_BLK - 1) / SCAN_BLK;
    int mmg = (N + 127) / 128;
    int pg = mmg < PGRID ? mmg : PGRID;

    // k_mm_mma kept at launch slot 4 for ncu capture.
    k_stats<<<NB_STATS, H>>>(x, N);                                        // 1
    k_fold1<<<1, H>>>(conv_feat_b, bn_feat_g, bn_feat_b, N, 1);            // 2
    k_fold2<<<H, H>>>(conv_feat_W);                                        // 3
    k_mm_mma<<<pg, 512, SMEM_MM>>>(x, nullptr, nullptr, nullptr, bufA, N, mmg, 0); // 4 <- profiled
    k_detect<<<1, 32>>>(ei, batch, E, N);                                  // 5
    k_zero<<<256, 256>>>(N);                                               // 6
    k_hist<<<(E + 255) / 256, 256>>>(ei, E);                               // 7
    k_scan1<<<nb, SCAN_BLK>>>(N);                                          // 8
    k_scan2<<<1, 32>>>(nb);                                                // 9
    k_scan3<<<(N + 255) / 256, 256>>>(N, E);                               // 10
    k_fill<<<(E + 255) / 256, 256>>>(ei, E);                               // 11
    k_gather<<<(N + GW - 1) / GW, 32 * GW>>>(bufA, xh, xl, N);             // 12

    // layers 1..3
    for (int l = 0; l < 3; l++) {
        k_fold1<<<1, H>>>(conv_b + l * H, bn_conv_g + l * H, bn_conv_b + l * H, N, 0);
        k_fold2<<<H, H>>>(conv_W + (size_t)l * H * H);
        k_mm_mma<<<pg, 512, SMEM_MM>>>(nullptr, xh, xl, nullptr, bufA, N, mmg, 1);
        k_gather<<<(N + GW - 1) / GW, 32 * GW>>>(bufA, xh, xl, N);
    }

    // gate MLP + pooling
    k_prepgate<<<H, H>>>(gate_W1);
    k_mm_mma<<<pg, 512, SMEM_MM>>>(nullptr, xh, xl, gate_b1, bufA, N, mmg, 2);
    k_gatepool<<<((size_t)N * 32 + 255) / 256, 256>>>(bufA, xh, xl, gate_W2, gate_b2, batch, N);

    // fc + classifier + log_softmax
    k_foldfc<<<1, H>>>(fc_W, fc_b, bn_fc_g, bn_fc_b);
    k_final<<<NGR, H>>>(cls_W, cls_b, (float*)d_out);
}

// round 12
// speedup vs baseline: 1.1379x; 1.1379x over previous
#include <cuda_runtime.h>
#include <cuda_fp16.h>
#include <math.h>
#include <stdint.h>

#define H 128
#define NGR 256
#define NCLS 10
#define NMAX 50048
#define EMAX 600064
#define NB_STATS 256
#define SCAN_BLK 512
#define MAX_SB ((NMAX + SCAN_BLK - 1) / SCAN_BLK)

#define ST32 68                          // uint32 stride of fp16 smem rows
#define ABUF (2 * 128 * ST32)            // one A double-buffer slot (hi+lo)
#define SMEM_MM ((6 * 128 * ST32) * 4)   // 2 A bufs + B(hi,lo) = 208896 B
#define PGRID 148

// ---------------- device scratch ----------------
__device__ float g_bufA[(size_t)NMAX * H];               // GEMM output p (fp32)
__device__ __align__(16) __half g_XH[(size_t)NMAX * H];  // activations hi
__device__ __align__(16) __half g_XL[(size_t)NMAX * H];  // activations lo
__device__ float g_dinv[NMAX];
__device__ int   g_deg[NMAX];
__device__ int   g_rowptr[NMAX + 1];
__device__ int   g_cursor[NMAX];
__device__ int   g_srcs[EMAX];
__device__ int   g_bsum[MAX_SB + 1];
__device__ float g_psum[NB_STATS * H];
__device__ float g_psq[NB_STATS * H];
__device__ float g_svec[H];
__device__ float g_tvec[H];
__device__ float g_Wf[H * H];
__device__ __align__(16) __half g_Bh[H * H];             // weight hi, [n][k]
__device__ __align__(16) __half g_Bl[H * H];             // weight lo, [n][k]
__device__ float g_cvec[H];
__device__ float g_bf[H];
__device__ float g_pool[NGR * H];
__device__ int   g_flags[2];

// ---------------- helpers ----------------
__device__ __forceinline__ uint32_t pack2(__half a, __half b) {
    return (uint32_t)__half_as_ushort(a) | ((uint32_t)__half_as_ushort(b) << 16);
}
__device__ __forceinline__ void split16(float x, __half& hi, __half& lo) {
    hi = __float2half_rn(x);
    lo = __float2half_rn(x - __half2float(hi));
}
__device__ __forceinline__ void mma16(float* acc, uint32_t a0, uint32_t a1, uint32_t a2,
                                      uint32_t a3, uint32_t b0, uint32_t b1) {
    asm volatile(
        "mma.sync.aligned.m16n8k16.row.col.f32.f16.f16.f32 "
        "{%0,%1,%2,%3},{%4,%5,%6,%7},{%8,%9},{%0,%1,%2,%3};"
        : "+f"(acc[0]), "+f"(acc[1]), "+f"(acc[2]), "+f"(acc[3])
        : "r"(a0), "r"(a1), "r"(a2), "r"(a3), "r"(b0), "r"(b1));
}
__device__ __forceinline__ void cp16(uint32_t dst, const void* src, int sz) {
    asm volatile("cp.async.cg.shared.global [%0], [%1], 16, %2;"
                 :: "r"(dst), "l"(src), "r"(sz) : "memory");
}

// ---------------- dtype-flexible index load ----------------
__device__ __forceinline__ int edge_idx(const void* p, long long i) {
    return g_flags[0] ? (int)((const long long*)p)[i] : ((const int*)p)[i];
}

__global__ void k_detect(const void* ei, const void* bt, int E, int N) {
    if (threadIdx.x == 0 && blockIdx.x == 0) {
        const unsigned long long* e64 = (const unsigned long long*)ei;
        int f = 1;
        for (int j = 0; j < 32; j++)
            if (e64[j] >= (1ULL << 31)) { f = 0; break; }
        g_flags[0] = f;
        const unsigned long long* b64 = (const unsigned long long*)bt;
        int f2 = 1;
        int half = N / 2;
        for (int j = half - 32; j < half; j++)
            if (b64[j] >= (1ULL << 31)) { f2 = 0; break; }
        g_flags[1] = f2;
    }
}

__global__ void k_zero(int N) {
    int tot = (N > NGR * H) ? N : (NGR * H);
    for (int i = blockIdx.x * blockDim.x + threadIdx.x; i < tot; i += gridDim.x * blockDim.x) {
        if (i < N) g_deg[i] = 0;
        if (i < NGR * H) g_pool[i] = 0.f;
    }
}

__global__ void k_hist(const void* ei, int E) {
    int e = blockIdx.x * blockDim.x + threadIdx.x;
    if (e < E) atomicAdd(&g_deg[edge_idx(ei, (long long)E + e)], 1);
}

// ---------------- CSR build (scan1 also emits dinv) ----------------
__global__ void k_scan1(int N) {
    __shared__ int sh[SCAN_BLK];
    int t = threadIdx.x;
    int i = blockIdx.x * SCAN_BLK + t;
    int v = (i < N) ? g_deg[i] : 0;
    if (i < N) g_dinv[i] = rsqrtf((float)v + 1.0f);
    sh[t] = v;
    __syncthreads();
    for (int off = 1; off < SCAN_BLK; off <<= 1) {
        int add = (t >= off) ? sh[t - off] : 0;
        __syncthreads();
        sh[t] += add;
        __syncthreads();
    }
    if (i < N) g_rowptr[i] = sh[t] - v;
    if (t == SCAN_BLK - 1) g_bsum[blockIdx.x] = sh[t];
}

__global__ void k_scan2(int nb) {
    if (threadIdx.x == 0 && blockIdx.x == 0) {
        int acc = 0;
        for (int b = 0; b < nb; b++) { int v = g_bsum[b]; g_bsum[b] = acc; acc += v; }
    }
}

__global__ void k_scan3(int N, int E) {
    int i = blockIdx.x * blockDim.x + threadIdx.x;
    if (i < N) {
        int r = g_rowptr[i] + g_bsum[i / SCAN_BLK];
        g_rowptr[i] = r;
        g_cursor[i] = r;
    }
    if (i == 0) g_rowptr[N] = E;
}

__global__ void k_fill(const void* ei, int E) {
    int e = blockIdx.x * blockDim.x + threadIdx.x;
    if (e < E) {
        int s = edge_idx(ei, e);
        int d = edge_idx(ei, (long long)E + e);
        g_srcs[atomicAdd(&g_cursor[d], 1)] = s;
    }
}

// ---------------- layer-0: BN stats over x + write x as fp16 hi/lo images ----------------
__global__ void k_statsplit(const float* __restrict__ x, __half* __restrict__ xh,
                            __half* __restrict__ xl, int N) {
    int j = threadIdx.x;
    int b = blockIdx.x;
    float s = 0.f, q = 0.f;
    for (int r = b; r < N; r += NB_STATS) {
        float v = x[(size_t)r * H + j];
        s += v; q += v * v;
        __half hh, hl;
        split16(v, hh, hl);
        xh[(size_t)r * H + j] = hh;
        xl[(size_t)r * H + j] = hl;
    }
    g_psum[b * H + j] = s;
    g_psq[b * H + j]  = q;
}

// ---------------- BN stats over fp16 hi/lo activation images ----------------
__global__ void k_stats16(const __half* __restrict__ xh, const __half* __restrict__ xl, int N) {
    int j = threadIdx.x;
    int b = blockIdx.x;
    float s = 0.f, q = 0.f;
    for (int r = b; r < N; r += NB_STATS) {
        float v = __half2float(xh[(size_t)r * H + j]) + __half2float(xl[(size_t)r * H + j]);
        s += v; q += v * v;
    }
    g_psum[b * H + j] = s;
    g_psq[b * H + j]  = q;
}

// fold stage 1: finalize BN stats -> s,t vectors
__global__ void k_fold1(const float* __restrict__ bias_in, const float* __restrict__ gamma,
                        const float* __restrict__ beta, int Nrows) {
    int j = threadIdx.x;
    float s = 0.f, q = 0.f;
    for (int b = 0; b < NB_STATS; b++) { s += g_psum[b * H + j]; q += g_psq[b * H + j]; }
    float mean = s / (float)Nrows;
    float var  = q / (float)Nrows - mean * mean;
    float sj = rsqrtf(var + 1e-5f) * gamma[j];
    g_svec[j] = sj;
    g_tvec[j] = beta[j] - mean * sj;
    g_bf[j] = bias_in[j];
}

// fold stage 2 (128 blocks): weight split image [n][k] + cvec
__global__ void k_fold2(const float* __restrict__ W) {
    __shared__ float red[4];
    int n = blockIdx.x, k = threadIdx.x;
    float wkn = W[k * H + n];
    float w = g_svec[k] * wkn;
    __half hh, hl;
    split16(w, hh, hl);
    g_Bh[n * H + k] = hh;
    g_Bl[n * H + k] = hl;
    float c = g_tvec[k] * wkn;
#pragma unroll
    for (int o = 16; o; o >>= 1) c += __shfl_xor_sync(0xffffffffu, c, o);
    if ((k & 31) == 0) red[k >> 5] = c;
    __syncthreads();
    if (k == 0) g_cvec[n] = red[0] + red[1] + red[2] + red[3];
}

__global__ void k_prepgate(const float* __restrict__ W) {
    int n = blockIdx.x, k = threadIdx.x;
    float w = W[k * H + n];
    __half hh, hl;
    split16(w, hh, hl);
    g_Bh[n * H + k] = hh;
    g_Bl[n * H + k] = hl;
}

// ---------------- persistent pipelined tensor-core GEMM (fp16 3-term split) ----------------
// A from pre-split fp16 images; double-buffered cp.async staging; B staged once.
// mode 0: out = acc + cvec[col]     mode 1: out = relu(acc + bias[col])
__global__ void __launch_bounds__(512, 1)
k_mm_mma(const __half* __restrict__ AH, const __half* __restrict__ AL,
         const float* __restrict__ bias, float* __restrict__ out,
         int nrows, int ntiles, int mode) {
    extern __shared__ uint32_t smu[];
    uint32_t* BsH = smu + 2 * ABUF;
    uint32_t* BsL = smu + 2 * ABUF + 128 * ST32;
    uint32_t sbase;
    asm("{ .reg .u64 t; cvta.to.shared.u64 t, %1; cvt.u32.u64 %0, t; }"
        : "=r"(sbase) : "l"(smu));
    int tid = threadIdx.x;
    int wid = tid >> 5, lane = tid & 31;
    int wm = wid & 3, wn = wid >> 2;
    int g = lane >> 2, t = lane & 3;

    // ---- stage B once ----
    {
        const uint4* bh4 = (const uint4*)g_Bh;
        const uint4* bl4 = (const uint4*)g_Bl;
#pragma unroll
        for (int i = 0; i < 4; i++) {
            int f = i * 512 + tid;
            int n = f >> 4;
            int c = (f & 15) << 2;
            uint4 vh = bh4[f];
            uint4 vl = bl4[f];
            *(uint4*)&BsH[n * ST32 + c] = vh;
            *(uint4*)&BsL[n * ST32 + c] = vl;
        }
    }

    const uint4* ah4 = (const uint4*)AH;
    const uint4* al4 = (const uint4*)AL;

    // async A staging of one tile into buffer `bsel`
    auto stageA = [&](int tile, int bsel) {
        uint32_t base = sbase + (uint32_t)bsel * (ABUF * 4);
        int row0 = tile * 128;
#pragma unroll
        for (int i = 0; i < 4; i++) {
            int f = i * 512 + tid;
            int r = f >> 4;
            int cu = f & 15;
            int gr = row0 + r;
            int sz = (gr < nrows) ? 16 : 0;
            int grc = (gr < nrows) ? gr : 0;
            uint32_t dH = base + (uint32_t)(r * ST32 + cu * 4) * 4u;
            cp16(dH, ah4 + (size_t)grc * 16 + cu, sz);
            cp16(dH + 128u * ST32 * 4u, al4 + (size_t)grc * 16 + cu, sz);
        }
        asm volatile("cp.async.commit_group;" ::: "memory");
    };

    int buf = 0;
    int first = blockIdx.x;
    if (first < ntiles) stageA(first, 0);

    for (int tile = first; tile < ntiles; tile += gridDim.x) {
        int next = tile + gridDim.x;
        asm volatile("cp.async.wait_group 0;" ::: "memory");
        __syncthreads();
        if (next < ntiles) stageA(next, buf ^ 1);

        uint32_t* AsH = smu + buf * ABUF;
        uint32_t* AsL = AsH + 128 * ST32;

        float acc[2][4][4];
#pragma unroll
        for (int mf = 0; mf < 2; mf++)
#pragma unroll
            for (int nf = 0; nf < 4; nf++)
#pragma unroll
                for (int k = 0; k < 4; k++) acc[mf][nf][k] = 0.f;

#pragma unroll
        for (int ki = 0; ki < 8; ki++) {
            int k0 = ki * 8;
            uint32_t ah[2][4], al[2][4];
#pragma unroll
            for (int mf = 0; mf < 2; mf++) {
                int rA = (wm * 32 + mf * 16 + g) * ST32 + k0 + t;
                ah[mf][0] = AsH[rA];             ah[mf][1] = AsH[rA + 8 * ST32];
                ah[mf][2] = AsH[rA + 4];         ah[mf][3] = AsH[rA + 8 * ST32 + 4];
                al[mf][0] = AsL[rA];             al[mf][1] = AsL[rA + 8 * ST32];
                al[mf][2] = AsL[rA + 4];         al[mf][3] = AsL[rA + 8 * ST32 + 4];
            }
            uint32_t bh[4][2], bl[4][2];
#pragma unroll
            for (int nf = 0; nf < 4; nf++) {
                int rB = (wn * 32 + nf * 8 + g) * ST32 + k0 + t;
                bh[nf][0] = BsH[rB];             bh[nf][1] = BsH[rB + 4];
                bl[nf][0] = BsL[rB];             bl[nf][1] = BsL[rB + 4];
            }
#pragma unroll
            for (int mf = 0; mf < 2; mf++)
#pragma unroll
                for (int nf = 0; nf < 4; nf++) {
                    mma16(acc[mf][nf], ah[mf][0], ah[mf][1], ah[mf][2], ah[mf][3],
                          bh[nf][0], bh[nf][1]);
                    mma16(acc[mf][nf], al[mf][0], al[mf][1], al[mf][2], al[mf][3],
                          bh[nf][0], bh[nf][1]);
                    mma16(acc[mf][nf], ah[mf][0], ah[mf][1], ah[mf][2], ah[mf][3],
                          bl[nf][0], bl[nf][1]);
                }
        }

        // ---- epilogue ----
        int row0 = tile * 128;
#pragma unroll
        for (int mf = 0; mf < 2; mf++) {
            int r0 = row0 + wm * 32 + mf * 16 + g;
            int r1 = r0 + 8;
#pragma unroll
            for (int nf = 0; nf < 4; nf++) {
                int col = wn * 32 + nf * 8 + t * 2;
                float* a = acc[mf][nf];
                if (mode == 0) {
                    float c0 = g_cvec[col], c1 = g_cvec[col + 1];
                    if (r0 < nrows)
                        *(float2*)&out[(size_t)r0 * H + col] = make_float2(a[0] + c0, a[1] + c1);
                    if (r1 < nrows)
                        *(float2*)&out[(size_t)r1 * H + col] = make_float2(a[2] + c0, a[3] + c1);
                } else {
                    float b0 = bias[col], b1 = bias[col + 1];
                    if (r0 < nrows)
                        *(float2*)&out[(size_t)r0 * H + col] =
                            make_float2(fmaxf(a[0] + b0, 0.f), fmaxf(a[1] + b1, 0.f));
                    if (r1 < nrows)
                        *(float2*)&out[(size_t)r1 * H + col] =
                            make_float2(fmaxf(a[2] + b0, 0.f), fmaxf(a[3] + b1, 0.f));
                }
            }
        }
        buf ^= 1;
    }
}

// ---------------- CSR gather (independent warp per node) + fp16 hi/lo output ----------------
__global__ void k_gather(const float* __restrict__ p, __half* __restrict__ oh,
                         __half* __restrict__ ol, int N) {
    int w = (blockIdx.x * blockDim.x + threadIdx.x) >> 5;
    int lane = threadIdx.x & 31;
    if (w >= N) return;
    float dw = g_dinv[w];
    float4 self = *(const float4*)&p[(size_t)w * H + lane * 4];
    float4 acc = make_float4(self.x * dw, self.y * dw, self.z * dw, self.w * dw);
    int beg = g_rowptr[w], end = g_rowptr[w + 1];
    int e = beg;
    for (; e + 3 < end; e += 4) {
        int s0 = g_srcs[e], s1 = g_srcs[e + 1], s2 = g_srcs[e + 2], s3 = g_srcs[e + 3];
        float d0 = g_dinv[s0], d1 = g_dinv[s1], d2 = g_dinv[s2], d3 = g_dinv[s3];
        float4 v0 = *(const float4*)&p[(size_t)s0 * H + lane * 4];
        float4 v1 = *(const float4*)&p[(size_t)s1 * H + lane * 4];
        float4 v2 = *(const float4*)&p[(size_t)s2 * H + lane * 4];
        float4 v3 = *(const float4*)&p[(size_t)s3 * H + lane * 4];
        acc.x = fmaf(v0.x, d0, acc.x); acc.y = fmaf(v0.y, d0, acc.y);
        acc.z = fmaf(v0.z, d0, acc.z); acc.w = fmaf(v0.w, d0, acc.w);
        acc.x = fmaf(v1.x, d1, acc.x); acc.y = fmaf(v1.y, d1, acc.y);
        acc.z = fmaf(v1.z, d1, acc.z); acc.w = fmaf(v1.w, d1, acc.w);
        acc.x = fmaf(v2.x, d2, acc.x); acc.y = fmaf(v2.y, d2, acc.y);
        acc.z = fmaf(v2.z, d2, acc.z); acc.w = fmaf(v2.w, d2, acc.w);
        acc.x = fmaf(v3.x, d3, acc.x); acc.y = fmaf(v3.y, d3, acc.y);
        acc.z = fmaf(v3.z, d3, acc.z); acc.w = fmaf(v3.w, d3, acc.w);
    }
    for (; e < end; e++) {
        int s = g_srcs[e];
        float ds = g_dinv[s];
        float4 v = *(const float4*)&p[(size_t)s * H + lane * 4];
        acc.x = fmaf(v.x, ds, acc.x); acc.y = fmaf(v.y, ds, acc.y);
        acc.z = fmaf(v.z, ds, acc.z); acc.w = fmaf(v.w, ds, acc.w);
    }
    float4 bb = *(const float4*)&g_bf[lane * 4];
    float4 o;
    o.x = fmaxf(fmaf(acc.x, dw, bb.x), 0.f);
    o.y = fmaxf(fmaf(acc.y, dw, bb.y), 0.f);
    o.z = fmaxf(fmaf(acc.z, dw, bb.z), 0.f);
    o.w = fmaxf(fmaf(acc.w, dw, bb.w), 0.f);
    __half h0, l0, h1, l1, h2, l2, h3, l3;
    split16(o.x, h0, l0); split16(o.y, h1, l1);
    split16(o.z, h2, l2); split16(o.w, h3, l3);
    *(uint2*)&oh[(size_t)w * H + lane * 4] = make_uint2(pack2(h0, h1), pack2(h2, h3));
    *(uint2*)&ol[(size_t)w * H + lane * 4] = make_uint2(pack2(l0, l1), pack2(l2, l3));
}

// ---------------- gate scalar + weighted pooling ----------------
__global__ void k_gatepool(const float* __restrict__ r, const __half* __restrict__ hh,
                           const __half* __restrict__ hl, const float* __restrict__ w2,
                           const float* __restrict__ b2, const void* batch, int N) {
    int w = (blockIdx.x * blockDim.x + threadIdx.x) >> 5;
    int lane = threadIdx.x & 31;
    if (w >= N) return;
    float4 rv = *(const float4*)&r[(size_t)w * H + lane * 4];
    float4 wv = *(const float4*)&w2[lane * 4];
    float d = rv.x * wv.x + rv.y * wv.y + rv.z * wv.z + rv.w * wv.w;
#pragma unroll
    for (int o = 16; o; o >>= 1) d += __shfl_xor_sync(0xffffffffu, d, o);
    float gate = 1.f / (1.f + expf(-(d + b2[0])));
    int b = g_flags[1] ? (int)((const long long*)batch)[w] : ((const int*)batch)[w];
    const __half2* ph = (const __half2*)(hh + (size_t)w * H) + lane * 2;
    const __half2* pl = (const __half2*)(hl + (size_t)w * H) + lane * 2;
    float2 a0 = __half22float2(ph[0]), a1 = __half22float2(ph[1]);
    float2 c0 = __half22float2(pl[0]), c1 = __half22float2(pl[1]);
    float4 hv = make_float4(a0.x + c0.x, a0.y + c0.y, a1.x + c1.x, a1.y + c1.y);
    float* dst = &g_pool[b * H + lane * 4];
    atomicAdd(dst + 0, hv.x * gate);
    atomicAdd(dst + 1, hv.y * gate);
    atomicAdd(dst + 2, hv.z * gate);
    atomicAdd(dst + 3, hv.w * gate);
}

// ---------------- BN over pooled graphs, folded into fc ----------------
__global__ void k_foldfc(const float* __restrict__ fcW, const float* __restrict__ fcb,
                         const float* __restrict__ gg, const float* __restrict__ gb) {
    int j = threadIdx.x;
    float s = 0.f, q = 0.f;
    for (int r = 0; r < NGR; r++) {
        float v = g_pool[r * H + j];
        s += v; q += v * v;
    }
    float mean = s / (float)NGR;
    float var = q / (float)NGR - mean * mean;
    float sj = rsqrtf(var + 1e-5f) * gg[j];
    float tj = gb[j] - mean * sj;
    __shared__ float ssh[H], tsh[H];
    ssh[j] = sj;
    tsh[j] = tj;
    __syncthreads();
    float bb = fcb[j];
#pragma unroll 4
    for (int r = 0; r < H; r++) {
        float wrj = fcW[r * H + j];
        g_Wf[r * H + j] = ssh[r] * wrj;
        bb += tsh[r] * wrj;
    }
    g_bf[j] = bb;
}

// ---------------- fc + classifier + log_softmax ----------------
__global__ void k_final(const float* __restrict__ clsW, const float* __restrict__ clsb,
                        float* __restrict__ out) {
    __shared__ float gs[H], ys[H], ls[NCLS];
    int g = blockIdx.x, t = threadIdx.x;
    gs[t] = g_pool[g * H + t];
    __syncthreads();
    float a = g_bf[t];
#pragma unroll 8
    for (int j = 0; j < H; j++) a += gs[j] * g_Wf[j * H + t];
    ys[t] = fmaxf(a, 0.f);
    __syncthreads();
    if (t < NCLS) {
        float l = clsb[t];
        for (int k = 0; k < H; k++) l += ys[k] * clsW[k * NCLS + t];
        ls[t] = l;
    }
    __syncthreads();
    if (t == 0) {
        float m = ls[0];
        for (int c = 1; c < NCLS; c++) m = fmaxf(m, ls[c]);
        float se = 0.f;
        for (int c = 0; c < NCLS; c++) se += expf(ls[c] - m);
        float lse = m + logf(se);
        for (int c = 0; c < NCLS; c++) out[g * NCLS + c] = ls[c] - lse;
    }
}

// ---------------- host orchestration ----------------
extern "C" void kernel_launch(void* const* d_in, const int* in_sizes, int n_in,
                              void* d_out, int out_size) {
    const float* x           = (const float*)d_in[0];
    const void*  ei          = d_in[1];
    const void*  batch       = d_in[2];
    const float* bn_feat_g   = (const float*)d_in[3];
    const float* bn_feat_b   = (const float*)d_in[4];
    const float* conv_feat_W = (const float*)d_in[5];
    const float* conv_feat_b = (const float*)d_in[6];
    const float* conv_W      = (const float*)d_in[7];
    const float* conv_b      = (const float*)d_in[8];
    const float* bn_conv_g   = (const float*)d_in[9];
    const float* bn_conv_b   = (const float*)d_in[10];
    const float* gate_W1     = (const float*)d_in[11];
    const float* gate_b1     = (const float*)d_in[12];
    const float* gate_W2     = (const float*)d_in[13];
    const float* gate_b2     = (const float*)d_in[14];
    const float* fc_W        = (const float*)d_in[15];
    const float* fc_b        = (const float*)d_in[16];
    const float* bn_fc_g     = (const float*)d_in[17];
    const float* bn_fc_b     = (const float*)d_in[18];
    const float* cls_W       = (const float*)d_in[19];
    const float* cls_b       = (const float*)d_in[20];

    int N = in_sizes[0] / H;
    int E = in_sizes[1] / 2;

    float* bufA = nullptr;
    __half *xh = nullptr, *xl = nullptr;
    cudaGetSymbolAddress((void**)&bufA, g_bufA);
    cudaGetSymbolAddress((void**)&xh, g_XH);
    cudaGetSymbolAddress((void**)&xl, g_XL);

    cudaFuncSetAttribute(k_mm_mma, cudaFuncAttributeMaxDynamicSharedMemorySize, SMEM_MM);

    int nb = (N + SCAN_BLK - 1) / SCAN_BLK;
    int mmg = (N + 127) / 128;
    int pg = mmg < PGRID ? mmg : PGRID;

    // k_mm_mma at launch slot 4 for ncu capture.
    k_statsplit<<<NB_STATS, H>>>(x, xh, xl, N);                            // 1
    k_fold1<<<1, H>>>(conv_feat_b, bn_feat_g, bn_feat_b, N);               // 2
    k_fold2<<<H, H>>>(conv_feat_W);                                        // 3
    k_mm_mma<<<pg, 512, SMEM_MM>>>(xh, xl, nullptr, bufA, N, mmg, 0);      // 4 <- profiled
    k_detect<<<1, 32>>>(ei, batch, E, N);                                  // 5
    k_zero<<<256, 256>>>(N);                                               // 6
    k_hist<<<(E + 255) / 256, 256>>>(ei, E);                               // 7
    k_scan1<<<nb, SCAN_BLK>>>(N);                                          // 8
    k_scan2<<<1, 32>>>(nb);                                                // 9
    k_scan3<<<(N + 255) / 256, 256>>>(N, E);                               // 10
    k_fill<<<(E + 255) / 256, 256>>>(ei, E);                               // 11
    k_gather<<<(N + 7) / 8, 256>>>(bufA, xh, xl, N);                       // 12

    // layers 1..3
    for (int l = 0; l < 3; l++) {
        k_stats16<<<NB_STATS, H>>>(xh, xl, N);
        k_fold1<<<1, H>>>(conv_b + l * H, bn_conv_g + l * H, bn_conv_b + l * H, N);
        k_fold2<<<H, H>>>(conv_W + (size_t)l * H * H);
        k_mm_mma<<<pg, 512, SMEM_MM>>>(xh, xl, nullptr, bufA, N, mmg, 0);
        k_gather<<<(N + 7) / 8, 256>>>(bufA, xh, xl, N);
    }

    // gate MLP + pooling
    k_prepgate<<<H, H>>>(gate_W1);
    k_mm_mma<<<pg, 512, SMEM_MM>>>(xh, xl, gate_b1, bufA, N, mmg, 1);
    k_gatepool<<<((size_t)N * 32 + 255) / 256, 256>>>(bufA, xh, xl, gate_W2, gate_b2, batch, N);

    // fc + classifier + log_softmax
    k_foldfc<<<1, H>>>(fc_W, fc_b, bn_fc_g, bn_fc_b);
    k_final<<<NGR, H>>>(cls_W, cls_b, (float*)d_out);
}

// round 13
// speedup vs baseline: 1.1405x; 1.0023x over previous
#include <cuda_runtime.h>
#include <cuda_fp16.h>
#include <math.h>
#include <stdint.h>

#define H 128
#define NGR 256
#define NCLS 10
#define NMAX 50048
#define EMAX 600064
#define NB_STATS 256
#define SCAN_BLK 512
#define MAX_SB ((NMAX + SCAN_BLK - 1) / SCAN_BLK)

#define ST32 68                          // uint32 stride of fp16 smem rows
#define ABUF (2 * 128 * ST32)            // one A double-buffer slot (hi+lo)
#define SMEM_MM ((6 * 128 * ST32) * 4)   // 2 A bufs + B(hi,lo) = 208896 B
#define PGRID 148

// ---------------- device scratch ----------------
__device__ float g_bufA[(size_t)NMAX * H];               // GEMM output p (fp32)
__device__ __align__(16) __half g_XH[(size_t)NMAX * H];  // activations hi
__device__ __align__(16) __half g_XL[(size_t)NMAX * H];  // activations lo
__device__ float g_dinv[NMAX];
__device__ int   g_deg[NMAX];
__device__ int   g_rowptr[NMAX + 1];
__device__ int   g_cursor[NMAX];
__device__ int   g_srcs[EMAX];
__device__ int   g_bsum[MAX_SB + 1];
__device__ float g_psum[NB_STATS * H];
__device__ float g_psq[NB_STATS * H];
__device__ float g_svec[H];
__device__ float g_tvec[H];
__device__ float g_Wf[H * H];
__device__ __align__(16) __half g_Bh[H * H];             // weight hi, [n][k]
__device__ __align__(16) __half g_Bl[H * H];             // weight lo, [n][k]
__device__ float g_cvec[H];
__device__ float g_bf[H];
__device__ float g_pool[NGR * H];
__device__ int   g_flags[2];

// ---------------- helpers ----------------
__device__ __forceinline__ uint32_t pack2(__half a, __half b) {
    return (uint32_t)__half_as_ushort(a) | ((uint32_t)__half_as_ushort(b) << 16);
}
__device__ __forceinline__ void split16(float x, __half& hi, __half& lo) {
    hi = __float2half_rn(x);
    lo = __float2half_rn(x - __half2float(hi));
}
// f32-accumulator fp16 mma
__device__ __forceinline__ void mma16(float* acc, uint32_t a0, uint32_t a1, uint32_t a2,
                                      uint32_t a3, uint32_t b0, uint32_t b1) {
    asm volatile(
        "mma.sync.aligned.m16n8k16.row.col.f32.f16.f16.f32 "
        "{%0,%1,%2,%3},{%4,%5,%6,%7},{%8,%9},{%0,%1,%2,%3};"
        : "+f"(acc[0]), "+f"(acc[1]), "+f"(acc[2]), "+f"(acc[3])
        : "r"(a0), "r"(a1), "r"(a2), "r"(a3), "r"(b0), "r"(b1));
}
// f16-accumulator fp16 mma (for small lo terms)
__device__ __forceinline__ void mma16h(uint32_t* acc, uint32_t a0, uint32_t a1, uint32_t a2,
                                       uint32_t a3, uint32_t b0, uint32_t b1) {
    asm volatile(
        "mma.sync.aligned.m16n8k16.row.col.f16.f16.f16.f16 "
        "{%0,%1},{%2,%3,%4,%5},{%6,%7},{%0,%1};"
        : "+r"(acc[0]), "+r"(acc[1])
        : "r"(a0), "r"(a1), "r"(a2), "r"(a3), "r"(b0), "r"(b1));
}
#define LDSM4(r0, r1, r2, r3, addr) \
    asm volatile("ldmatrix.sync.aligned.m8n8.x4.shared.b16 {%0,%1,%2,%3}, [%4];" \
                 : "=r"(r0), "=r"(r1), "=r"(r2), "=r"(r3) : "r"(addr))
__device__ __forceinline__ void cp16(uint32_t dst, const void* src, int sz) {
    asm volatile("cp.async.cg.shared.global [%0], [%1], 16, %2;"
                 :: "r"(dst), "l"(src), "r"(sz) : "memory");
}

// ---------------- dtype-flexible index load ----------------
__device__ __forceinline__ int edge_idx(const void* p, long long i) {
    return g_flags[0] ? (int)((const long long*)p)[i] : ((const int*)p)[i];
}

__global__ void k_detect(const void* ei, const void* bt, int E, int N) {
    if (threadIdx.x == 0 && blockIdx.x == 0) {
        const unsigned long long* e64 = (const unsigned long long*)ei;
        int f = 1;
        for (int j = 0; j < 32; j++)
            if (e64[j] >= (1ULL << 31)) { f = 0; break; }
        g_flags[0] = f;
        const unsigned long long* b64 = (const unsigned long long*)bt;
        int f2 = 1;
        int half = N / 2;
        for (int j = half - 32; j < half; j++)
            if (b64[j] >= (1ULL << 31)) { f2 = 0; break; }
        g_flags[1] = f2;
    }
}

__global__ void k_zero(int N) {
    int tot = (N > NGR * H) ? N : (NGR * H);
    for (int i = blockIdx.x * blockDim.x + threadIdx.x; i < tot; i += gridDim.x * blockDim.x) {
        if (i < N) g_deg[i] = 0;
        if (i < NGR * H) g_pool[i] = 0.f;
    }
}

__global__ void k_hist(const void* ei, int E) {
    int e = blockIdx.x * blockDim.x + threadIdx.x;
    if (e < E) atomicAdd(&g_deg[edge_idx(ei, (long long)E + e)], 1);
}

// ---------------- CSR build (scan1 also emits dinv) ----------------
__global__ void k_scan1(int N) {
    __shared__ int sh[SCAN_BLK];
    int t = threadIdx.x;
    int i = blockIdx.x * SCAN_BLK + t;
    int v = (i < N) ? g_deg[i] : 0;
    if (i < N) g_dinv[i] = rsqrtf((float)v + 1.0f);
    sh[t] = v;
    __syncthreads();
    for (int off = 1; off < SCAN_BLK; off <<= 1) {
        int add = (t >= off) ? sh[t - off] : 0;
        __syncthreads();
        sh[t] += add;
        __syncthreads();
    }
    if (i < N) g_rowptr[i] = sh[t] - v;
    if (t == SCAN_BLK - 1) g_bsum[blockIdx.x] = sh[t];
}

__global__ void k_scan2(int nb) {
    if (threadIdx.x == 0 && blockIdx.x == 0) {
        int acc = 0;
        for (int b = 0; b < nb; b++) { int v = g_bsum[b]; g_bsum[b] = acc; acc += v; }
    }
}

__global__ void k_scan3(int N, int E) {
    int i = blockIdx.x * blockDim.x + threadIdx.x;
    if (i < N) {
        int r = g_rowptr[i] + g_bsum[i / SCAN_BLK];
        g_rowptr[i] = r;
        g_cursor[i] = r;
    }
    if (i == 0) g_rowptr[N] = E;
}

__global__ void k_fill(const void* ei, int E) {
    int e = blockIdx.x * blockDim.x + threadIdx.x;
    if (e < E) {
        int s = edge_idx(ei, e);
        int d = edge_idx(ei, (long long)E + e);
        g_srcs[atomicAdd(&g_cursor[d], 1)] = s;
    }
}

// ---------------- layer-0: BN stats over x + write x as fp16 hi/lo images ----------------
__global__ void k_statsplit(const float* __restrict__ x, __half* __restrict__ xh,
                            __half* __restrict__ xl, int N) {
    int j = threadIdx.x;
    int b = blockIdx.x;
    float s = 0.f, q = 0.f;
    for (int r = b; r < N; r += NB_STATS) {
        float v = x[(size_t)r * H + j];
        s += v; q += v * v;
        __half hh, hl;
        split16(v, hh, hl);
        xh[(size_t)r * H + j] = hh;
        xl[(size_t)r * H + j] = hl;
    }
    g_psum[b * H + j] = s;
    g_psq[b * H + j]  = q;
}

// ---------------- BN stats over fp16 hi/lo activation images ----------------
__global__ void k_stats16(const __half* __restrict__ xh, const __half* __restrict__ xl, int N) {
    int j = threadIdx.x;
    int b = blockIdx.x;
    float s = 0.f, q = 0.f;
    for (int r = b; r < N; r += NB_STATS) {
        float v = __half2float(xh[(size_t)r * H + j]) + __half2float(xl[(size_t)r * H + j]);
        s += v; q += v * v;
    }
    g_psum[b * H + j] = s;
    g_psq[b * H + j]  = q;
}

// fold stage 1: finalize BN stats -> s,t vectors
__global__ void k_fold1(const float* __restrict__ bias_in, const float* __restrict__ gamma,
                        const float* __restrict__ beta, int Nrows) {
    int j = threadIdx.x;
    float s = 0.f, q = 0.f;
    for (int b = 0; b < NB_STATS; b++) { s += g_psum[b * H + j]; q += g_psq[b * H + j]; }
    float mean = s / (float)Nrows;
    float var  = q / (float)Nrows - mean * mean;
    float sj = rsqrtf(var + 1e-5f) * gamma[j];
    g_svec[j] = sj;
    g_tvec[j] = beta[j] - mean * sj;
    g_bf[j] = bias_in[j];
}

// fold stage 2 (128 blocks): weight split image [n][k] + cvec
__global__ void k_fold2(const float* __restrict__ W) {
    __shared__ float red[4];
    int n = blockIdx.x, k = threadIdx.x;
    float wkn = W[k * H + n];
    float w = g_svec[k] * wkn;
    __half hh, hl;
    split16(w, hh, hl);
    g_Bh[n * H + k] = hh;
    g_Bl[n * H + k] = hl;
    float c = g_tvec[k] * wkn;
#pragma unroll
    for (int o = 16; o; o >>= 1) c += __shfl_xor_sync(0xffffffffu, c, o);
    if ((k & 31) == 0) red[k >> 5] = c;
    __syncthreads();
    if (k == 0) g_cvec[n] = red[0] + red[1] + red[2] + red[3];
}

__global__ void k_prepgate(const float* __restrict__ W) {
    int n = blockIdx.x, k = threadIdx.x;
    float w = W[k * H + n];
    __half hh, hl;
    split16(w, hh, hl);
    g_Bh[n * H + k] = hh;
    g_Bl[n * H + k] = hl;
}

// ---------------- persistent pipelined tensor-core GEMM ----------------
// fp16 3-term split: hi*hi in f32-acc mma; lo*hi and hi*lo in f16-acc mma.
// ldmatrix fragment loads; cp.async double-buffered A; B staged once.
// mode 0: out = acc + cvec[col]     mode 1: out = relu(acc + bias[col])
__global__ void __launch_bounds__(512, 1)
k_mm_mma(const __half* __restrict__ AH, const __half* __restrict__ AL,
         const float* __restrict__ bias, float* __restrict__ out,
         int nrows, int ntiles, int mode) {
    extern __shared__ uint32_t smu[];
    uint32_t* BsH = smu + 2 * ABUF;
    uint32_t* BsL = smu + 2 * ABUF + 128 * ST32;
    uint32_t sbase;
    asm("{ .reg .u64 t; cvta.to.shared.u64 t, %1; cvt.u32.u64 %0, t; }"
        : "=r"(sbase) : "l"(smu));
    int tid = threadIdx.x;
    int wid = tid >> 5, lane = tid & 31;
    int wm = wid & 3, wn = wid >> 2;
    int g = lane >> 2, t = lane & 3;

    // ---- stage B once ----
    {
        const uint4* bh4 = (const uint4*)g_Bh;
        const uint4* bl4 = (const uint4*)g_Bl;
#pragma unroll
        for (int i = 0; i < 4; i++) {
            int f = i * 512 + tid;
            int n = f >> 4;
            int c = (f & 15) << 2;
            uint4 vh = bh4[f];
            uint4 vl = bl4[f];
            *(uint4*)&BsH[n * ST32 + c] = vh;
            *(uint4*)&BsL[n * ST32 + c] = vl;
        }
    }

    const uint4* ah4 = (const uint4*)AH;
    const uint4* al4 = (const uint4*)AL;

    auto stageA = [&](int tile, int bsel) {
        uint32_t base = sbase + (uint32_t)bsel * (ABUF * 4);
        int row0 = tile * 128;
#pragma unroll
        for (int i = 0; i < 4; i++) {
            int f = i * 512 + tid;
            int r = f >> 4;
            int cu = f & 15;
            int gr = row0 + r;
            int sz = (gr < nrows) ? 16 : 0;
            int grc = (gr < nrows) ? gr : 0;
            uint32_t dH = base + (uint32_t)(r * ST32 + cu * 4) * 4u;
            cp16(dH, ah4 + (size_t)grc * 16 + cu, sz);
            cp16(dH + 128u * ST32 * 4u, al4 + (size_t)grc * 16 + cu, sz);
        }
        asm volatile("cp.async.commit_group;" ::: "memory");
    };

    // ldmatrix per-lane byte offsets (within an A buffer / within B region)
    // A (16x16 tile at mf, ki): lanes 0-15 -> rows, lanes 16-31 -> k halves +8
    uint32_t aoff = ((uint32_t)((wm * 32 + (lane & 15)) * ST32 + ((lane >> 4) << 2))) * 4u;
    // B (pair of 8x16 tiles): lanes 0-7 rows n0..n0+7 k0, 8-15 same rows k+8,
    // 16-23 rows n0+8.. k0, 24-31 rows n0+8.. k+8
    uint32_t boff = ((uint32_t)((wn * 32 + ((lane >> 4) << 3) + (lane & 7)) * ST32 +
                                (((lane >> 3) & 1) << 2))) * 4u;
    uint32_t bH0 = sbase + (2u * ABUF) * 4u + boff;          // pair p=0 hi
    uint32_t bL0 = bH0 + 128u * ST32 * 4u;                   // pair p=0 lo

    int buf = 0;
    int first = blockIdx.x;
    if (first < ntiles) stageA(first, 0);

    for (int tile = first; tile < ntiles; tile += gridDim.x) {
        int next = tile + gridDim.x;
        asm volatile("cp.async.wait_group 0;" ::: "memory");
        __syncthreads();
        if (next < ntiles) stageA(next, buf ^ 1);

        uint32_t aH0 = sbase + (uint32_t)buf * (ABUF * 4) + aoff;
        uint32_t aL0 = aH0 + 128u * ST32 * 4u;

        float acc[2][4][4];
#pragma unroll
        for (int mf = 0; mf < 2; mf++)
#pragma unroll
            for (int nf = 0; nf < 4; nf++)
#pragma unroll
                for (int k = 0; k < 4; k++) acc[mf][nf][k] = 0.f;
        uint32_t lacc[2][4][2];
#pragma unroll
        for (int mf = 0; mf < 2; mf++)
#pragma unroll
            for (int nf = 0; nf < 4; nf++) { lacc[mf][nf][0] = 0u; lacc[mf][nf][1] = 0u; }

#pragma unroll
        for (int ki = 0; ki < 8; ki++) {
            uint32_t kb = (uint32_t)ki * 32u;
            uint32_t ah0[4], ah1[4], al0[4], al1[4];
            uint32_t bh0[4], bh1[4], bl0[4], bl1[4];
            LDSM4(ah0[0], ah0[1], ah0[2], ah0[3], aH0 + kb);
            LDSM4(ah1[0], ah1[1], ah1[2], ah1[3], aH0 + 16u * ST32 * 4u + kb);
            LDSM4(al0[0], al0[1], al0[2], al0[3], aL0 + kb);
            LDSM4(al1[0], al1[1], al1[2], al1[3], aL0 + 16u * ST32 * 4u + kb);
            LDSM4(bh0[0], bh0[1], bh0[2], bh0[3], bH0 + kb);
            LDSM4(bh1[0], bh1[1], bh1[2], bh1[3], bH0 + 16u * ST32 * 4u + kb);
            LDSM4(bl0[0], bl0[1], bl0[2], bl0[3], bL0 + kb);
            LDSM4(bl1[0], bl1[1], bl1[2], bl1[3], bL0 + 16u * ST32 * 4u + kb);

            // hi*hi in f32 acc
            mma16(acc[0][0], ah0[0], ah0[1], ah0[2], ah0[3], bh0[0], bh0[1]);
            mma16(acc[0][1], ah0[0], ah0[1], ah0[2], ah0[3], bh0[2], bh0[3]);
            mma16(acc[0][2], ah0[0], ah0[1], ah0[2], ah0[3], bh1[0], bh1[1]);
            mma16(acc[0][3], ah0[0], ah0[1], ah0[2], ah0[3], bh1[2], bh1[3]);
            mma16(acc[1][0], ah1[0], ah1[1], ah1[2], ah1[3], bh0[0], bh0[1]);
            mma16(acc[1][1], ah1[0], ah1[1], ah1[2], ah1[3], bh0[2], bh0[3]);
            mma16(acc[1][2], ah1[0], ah1[1], ah1[2], ah1[3], bh1[0], bh1[1]);
            mma16(acc[1][3], ah1[0], ah1[1], ah1[2], ah1[3], bh1[2], bh1[3]);
            // lo*hi + hi*lo in f16 acc (terms are O(2^-11): fp16 acc error ~2^-22)
            mma16h(lacc[0][0], al0[0], al0[1], al0[2], al0[3], bh0[0], bh0[1]);
            mma16h(lacc[0][0], ah0[0], ah0[1], ah0[2], ah0[3], bl0[0], bl0[1]);
            mma16h(lacc[0][1], al0[0], al0[1], al0[2], al0[3], bh0[2], bh0[3]);
            mma16h(lacc[0][1], ah0[0], ah0[1], ah0[2], ah0[3], bl0[2], bl0[3]);
            mma16h(lacc[0][2], al0[0], al0[1], al0[2], al0[3], bh1[0], bh1[1]);
            mma16h(lacc[0][2], ah0[0], ah0[1], ah0[2], ah0[3], bl1[0], bl1[1]);
            mma16h(lacc[0][3], al0[0], al0[1], al0[2], al0[3], bh1[2], bh1[3]);
            mma16h(lacc[0][3], ah0[0], ah0[1], ah0[2], ah0[3], bl1[2], bl1[3]);
            mma16h(lacc[1][0], al1[0], al1[1], al1[2], al1[3], bh0[0], bh0[1]);
            mma16h(lacc[1][0], ah1[0], ah1[1], ah1[2], ah1[3], bl0[0], bl0[1]);
            mma16h(lacc[1][1], al1[0], al1[1], al1[2], al1[3], bh0[2], bh0[3]);
            mma16h(lacc[1][1], ah1[0], ah1[1], ah1[2], ah1[3], bl0[2], bl0[3]);
            mma16h(lacc[1][2], al1[0], al1[1], al1[2], al1[3], bh1[0], bh1[1]);
            mma16h(lacc[1][2], ah1[0], ah1[1], ah1[2], ah1[3], bl1[0], bl1[1]);
            mma16h(lacc[1][3], al1[0], al1[1], al1[2], al1[3], bh1[2], bh1[3]);
            mma16h(lacc[1][3], ah1[0], ah1[1], ah1[2], ah1[3], bl1[2], bl1[3]);
        }

        // ---- epilogue: combine f16 lo-acc into f32 acc, add bias terms, store ----
        int row0 = tile * 128;
#pragma unroll
        for (int mf = 0; mf < 2; mf++) {
            int r0 = row0 + wm * 32 + mf * 16 + g;
            int r1 = r0 + 8;
#pragma unroll
            for (int nf = 0; nf < 4; nf++) {
                int col = wn * 32 + nf * 8 + t * 2;
                float* a = acc[mf][nf];
                float2 l0 = __half22float2(*reinterpret_cast<__half2*>(&lacc[mf][nf][0]));
                float2 l1 = __half22float2(*reinterpret_cast<__half2*>(&lacc[mf][nf][1]));
                float d0 = a[0] + l0.x, d1 = a[1] + l0.y;
                float d2 = a[2] + l1.x, d3 = a[3] + l1.y;
                if (mode == 0) {
                    float c0 = g_cvec[col], c1 = g_cvec[col + 1];
                    if (r0 < nrows)
                        *(float2*)&out[(size_t)r0 * H + col] = make_float2(d0 + c0, d1 + c1);
                    if (r1 < nrows)
                        *(float2*)&out[(size_t)r1 * H + col] = make_float2(d2 + c0, d3 + c1);
                } else {
                    float b0 = bias[col], b1 = bias[col + 1];
                    if (r0 < nrows)
                        *(float2*)&out[(size_t)r0 * H + col] =
                            make_float2(fmaxf(d0 + b0, 0.f), fmaxf(d1 + b1, 0.f));
                    if (r1 < nrows)
                        *(float2*)&out[(size_t)r1 * H + col] =
                            make_float2(fmaxf(d2 + b0, 0.f), fmaxf(d3 + b1, 0.f));
                }
            }
        }
        buf ^= 1;
    }
}

// ---------------- CSR gather (independent warp per node) + fp16 hi/lo output ----------------
__global__ void k_gather(const float* __restrict__ p, __half* __restrict__ oh,
                         __half* __restrict__ ol, int N) {
    int w = (blockIdx.x * blockDim.x + threadIdx.x) >> 5;
    int lane = threadIdx.x & 31;
    if (w >= N) return;
    float dw = g_dinv[w];
    float4 self = *(const float4*)&p[(size_t)w * H + lane * 4];
    float4 acc = make_float4(self.x * dw, self.y * dw, self.z * dw, self.w * dw);
    int beg = g_rowptr[w], end = g_rowptr[w + 1];
    int e = beg;
    for (; e + 3 < end; e += 4) {
        int s0 = g_srcs[e], s1 = g_srcs[e + 1], s2 = g_srcs[e + 2], s3 = g_srcs[e + 3];
        float d0 = g_dinv[s0], d1 = g_dinv[s1], d2 = g_dinv[s2], d3 = g_dinv[s3];
        float4 v0 = *(const float4*)&p[(size_t)s0 * H + lane * 4];
        float4 v1 = *(const float4*)&p[(size_t)s1 * H + lane * 4];
        float4 v2 = *(const float4*)&p[(size_t)s2 * H + lane * 4];
        float4 v3 = *(const float4*)&p[(size_t)s3 * H + lane * 4];
        acc.x = fmaf(v0.x, d0, acc.x); acc.y = fmaf(v0.y, d0, acc.y);
        acc.z = fmaf(v0.z, d0, acc.z); acc.w = fmaf(v0.w, d0, acc.w);
        acc.x = fmaf(v1.x, d1, acc.x); acc.y = fmaf(v1.y, d1, acc.y);
        acc.z = fmaf(v1.z, d1, acc.z); acc.w = fmaf(v1.w, d1, acc.w);
        acc.x = fmaf(v2.x, d2, acc.x); acc.y = fmaf(v2.y, d2, acc.y);
        acc.z = fmaf(v2.z, d2, acc.z); acc.w = fmaf(v2.w, d2, acc.w);
        acc.x = fmaf(v3.x, d3, acc.x); acc.y = fmaf(v3.y, d3, acc.y);
        acc.z = fmaf(v3.z, d3, acc.z); acc.w = fmaf(v3.w, d3, acc.w);
    }
    for (; e < end; e++) {
        int s = g_srcs[e];
        float ds = g_dinv[s];
        float4 v = *(const float4*)&p[(size_t)s * H + lane * 4];
        acc.x = fmaf(v.x, ds, acc.x); acc.y = fmaf(v.y, ds, acc.y);
        acc.z = fmaf(v.z, ds, acc.z); acc.w = fmaf(v.w, ds, acc.w);
    }
    float4 bb = *(const float4*)&g_bf[lane * 4];
    float4 o;
    o.x = fmaxf(fmaf(acc.x, dw, bb.x), 0.f);
    o.y = fmaxf(fmaf(acc.y, dw, bb.y), 0.f);
    o.z = fmaxf(fmaf(acc.z, dw, bb.z), 0.f);
    o.w = fmaxf(fmaf(acc.w, dw, bb.w), 0.f);
    __half h0, l0, h1, l1, h2, l2, h3, l3;
    split16(o.x, h0, l0); split16(o.y, h1, l1);
    split16(o.z, h2, l2); split16(o.w, h3, l3);
    *(uint2*)&oh[(size_t)w * H + lane * 4] = make_uint2(pack2(h0, h1), pack2(h2, h3));
    *(uint2*)&ol[(size_t)w * H + lane * 4] = make_uint2(pack2(l0, l1), pack2(l2, l3));
}

// ---------------- gate scalar + weighted pooling ----------------
__global__ void k_gatepool(const float* __restrict__ r, const __half* __restrict__ hh,
                           const __half* __restrict__ hl, const float* __restrict__ w2,
                           const float* __restrict__ b2, const void* batch, int N) {
    int w = (blockIdx.x * blockDim.x + threadIdx.x) >> 5;
    int lane = threadIdx.x & 31;
    if (w >= N) return;
    float4 rv = *(const float4*)&r[(size_t)w * H + lane * 4];
    float4 wv = *(const float4*)&w2[lane * 4];
    float d = rv.x * wv.x + rv.y * wv.y + rv.z * wv.z + rv.w * wv.w;
#pragma unroll
    for (int o = 16; o; o >>= 1) d += __shfl_xor_sync(0xffffffffu, d, o);
    float gate = 1.f / (1.f + expf(-(d + b2[0])));
    int b = g_flags[1] ? (int)((const long long*)batch)[w] : ((const int*)batch)[w];
    const __half2* ph = (const __half2*)(hh + (size_t)w * H) + lane * 2;
    const __half2* pl = (const __half2*)(hl + (size_t)w * H) + lane * 2;
    float2 a0 = __half22float2(ph[0]), a1 = __half22float2(ph[1]);
    float2 c0 = __half22float2(pl[0]), c1 = __half22float2(pl[1]);
    float4 hv = make_float4(a0.x + c0.x, a0.y + c0.y, a1.x + c1.x, a1.y + c1.y);
    float* dst = &g_pool[b * H + lane * 4];
    atomicAdd(dst + 0, hv.x * gate);
    atomicAdd(dst + 1, hv.y * gate);
    atomicAdd(dst + 2, hv.z * gate);
    atomicAdd(dst + 3, hv.w * gate);
}

// ---------------- BN over pooled graphs, folded into fc ----------------
__global__ void k_foldfc(const float* __restrict__ fcW, const float* __restrict__ fcb,
                         const float* __restrict__ gg, const float* __restrict__ gb) {
    int j = threadIdx.x;
    float s = 0.f, q = 0.f;
    for (int r = 0; r < NGR; r++) {
        float v = g_pool[r * H + j];
        s += v; q += v * v;
    }
    float mean = s / (float)NGR;
    float var = q / (float)NGR - mean * mean;
    float sj = rsqrtf(var + 1e-5f) * gg[j];
    float tj = gb[j] - mean * sj;
    __shared__ float ssh[H], tsh[H];
    ssh[j] = sj;
    tsh[j] = tj;
    __syncthreads();
    float bb = fcb[j];
#pragma unroll 4
    for (int r = 0; r < H; r++) {
        float wrj = fcW[r * H + j];
        g_Wf[r * H + j] = ssh[r] * wrj;
        bb += tsh[r] * wrj;
    }
    g_bf[j] = bb;
}

// ---------------- fc + classifier + log_softmax ----------------
__global__ void k_final(const float* __restrict__ clsW, const float* __restrict__ clsb,
                        float* __restrict__ out) {
    __shared__ float gs[H], ys[H], ls[NCLS];
    int g = blockIdx.x, t = threadIdx.x;
    gs[t] = g_pool[g * H + t];
    __syncthreads();
    float a = g_bf[t];
#pragma unroll 8
    for (int j = 0; j < H; j++) a += gs[j] * g_Wf[j * H + t];
    ys[t] = fmaxf(a, 0.f);
    __syncthreads();
    if (t < NCLS) {
        float l = clsb[t];
        for (int k = 0; k < H; k++) l += ys[k] * clsW[k * NCLS + t];
        ls[t] = l;
    }
    __syncthreads();
    if (t == 0) {
        float m = ls[0];
        for (int c = 1; c < NCLS; c++) m = fmaxf(m, ls[c]);
        float se = 0.f;
        for (int c = 0; c < NCLS; c++) se += expf(ls[c] - m);
        float lse = m + logf(se);
        for (int c = 0; c < NCLS; c++) out[g * NCLS + c] = ls[c] - lse;
    }
}

// ---------------- host orchestration ----------------
extern "C" void kernel_launch(void* const* d_in, const int* in_sizes, int n_in,
                              void* d_out, int out_size) {
    const float* x           = (const float*)d_in[0];
    const void*  ei          = d_in[1];
    const void*  batch       = d_in[2];
    const float* bn_feat_g   = (const float*)d_in[3];
    const float* bn_feat_b   = (const float*)d_in[4];
    const float* conv_feat_W = (const float*)d_in[5];
    const float* conv_feat_b = (const float*)d_in[6];
    const float* conv_W      = (const float*)d_in[7];
    const float* conv_b      = (const float*)d_in[8];
    const float* bn_conv_g   = (const float*)d_in[9];
    const float* bn_conv_b   = (const float*)d_in[10];
    const float* gate_W1     = (const float*)d_in[11];
    const float* gate_b1     = (const float*)d_in[12];
    const float* gate_W2     = (const float*)d_in[13];
    const float* gate_b2     = (const float*)d_in[14];
    const float* fc_W        = (const float*)d_in[15];
    const float* fc_b        = (const float*)d_in[16];
    const float* bn_fc_g     = (const float*)d_in[17];
    const float* bn_fc_b     = (const float*)d_in[18];
    const float* cls_W       = (const float*)d_in[19];
    const float* cls_b       = (const float*)d_in[20];

    int N = in_sizes[0] / H;
    int E = in_sizes[1] / 2;

    float* bufA = nullptr;
    __half *xh = nullptr, *xl = nullptr;
    cudaGetSymbolAddress((void**)&bufA, g_bufA);
    cudaGetSymbolAddress((void**)&xh, g_XH);
    cudaGetSymbolAddress((void**)&xl, g_XL);

    cudaFuncSetAttribute(k_mm_mma, cudaFuncAttributeMaxDynamicSharedMemorySize, SMEM_MM);

    int nb = (N + SCAN_BLK - 1) / SCAN_BLK;
    int mmg = (N + 127) / 128;
    int pg = mmg < PGRID ? mmg : PGRID;

    // k_mm_mma at launch slot 4 for ncu capture.
    k_statsplit<<<NB_STATS, H>>>(x, xh, xl, N);                            // 1
    k_fold1<<<1, H>>>(conv_feat_b, bn_feat_g, bn_feat_b, N);               // 2
    k_fold2<<<H, H>>>(conv_feat_W);                                        // 3
    k_mm_mma<<<pg, 512, SMEM_MM>>>(xh, xl, nullptr, bufA, N, mmg, 0);      // 4 <- profiled
    k_detect<<<1, 32>>>(ei, batch, E, N);                                  // 5
    k_zero<<<256, 256>>>(N);                                               // 6
    k_hist<<<(E + 255) / 256, 256>>>(ei, E);                               // 7
    k_scan1<<<nb, SCAN_BLK>>>(N);                                          // 8
    k_scan2<<<1, 32>>>(nb);                                                // 9
    k_scan3<<<(N + 255) / 256, 256>>>(N, E);                               // 10
    k_fill<<<(E + 255) / 256, 256>>>(ei, E);                               // 11
    k_gather<<<(N + 7) / 8, 256>>>(bufA, xh, xl, N);                       // 12

    // layers 1..3
    for (int l = 0; l < 3; l++) {
        k_stats16<<<NB_STATS, H>>>(xh, xl, N);
        k_fold1<<<1, H>>>(conv_b + l * H, bn_conv_g + l * H, bn_conv_b + l * H, N);
        k_fold2<<<H, H>>>(conv_W + (size_t)l * H * H);
        k_mm_mma<<<pg, 512, SMEM_MM>>>(xh, xl, nullptr, bufA, N, mmg, 0);
        k_gather<<<(N + 7) / 8, 256>>>(bufA, xh, xl, N);
    }

    // gate MLP + pooling
    k_prepgate<<<H, H>>>(gate_W1);
    k_mm_mma<<<pg, 512, SMEM_MM>>>(xh, xl, gate_b1, bufA, N, mmg, 1);
    k_gatepool<<<((size_t)N * 32 + 255) / 256, 256>>>(bufA, xh, xl, gate_W2, gate_b2, batch, N);

    // fc + classifier + log_softmax
    k_foldfc<<<1, H>>>(fc_W, fc_b, bn_fc_g, bn_fc_b);
    k_final<<<NGR, H>>>(cls_W, cls_b, (float*)d_out);
}